// round 15
// baseline (speedup 1.0000x reference)
#include <cuda_runtime.h>
#include <cuda_bf16.h>
#include <math.h>

// SimDiff: right[f,i] = cos(x[f,i], x[f+iv, i+1])      (i < tpf-1)
//          down [f,i] = cos(x[f,i], x[f+iv, i+width])  (i < tpf-width)
// else -1. Output: [right | down], each frames*tpf f32.
//
// Unified model (14 rounds): dur = max(L1-issued bytes, L2-side bytes) /
// ~12 TB/s. R14 fixed L1 (2-step warps, 2.5 streams/token); this round also
// fixes L2 via DIAGONAL PAIRING (iv==1): chain-A's down-target at frame f ==
// chain-B(delta+width-1)'s token at frame f+1, so pairing both chains in one
// CTA makes A's down-streams coincide with B's anchor-streams -> distinct
// tokens/CTA = 26 for 16 outputs (1.625x ideal L2 volume), while L1-issued
// stays 2.5x. Same 48-reg float2 body as R14; per-token validity flags
// (left-edge warps can have token1 valid with token0 invalid).

#define EPSN 1e-8f

// 2-step warp body: 5 float2 streams, 9 accumulators, norm chain via n1.
template <int NPL>
__device__ __forceinline__ void body2(
    const float* __restrict__ x,
    float* __restrict__ outR, float* __restrict__ outD,
    int t0, int t1,
    int ta0, int ta1, int ta2, int tc0, int tc1,
    bool v0, bool v1, bool vr0, bool vd0, bool vr1, bool vd1,
    int lane)
{
    const int D = NPL * 128;
    const float2* __restrict__ A0 =
        reinterpret_cast<const float2*>(x + (size_t)ta0 * D) + lane;
    const float2* __restrict__ A1 =
        reinterpret_cast<const float2*>(x + (size_t)ta1 * D) + lane;
    const float2* __restrict__ A2 =
        reinterpret_cast<const float2*>(x + (size_t)ta2 * D) + lane;
    const float2* __restrict__ C0 =
        reinterpret_cast<const float2*>(x + (size_t)tc0 * D) + lane;
    const float2* __restrict__ C1 =
        reinterpret_cast<const float2*>(x + (size_t)tc1 * D) + lane;

    float n0 = 0.f, n1 = 0.f, n2 = 0.f;          // |a0|^2 |a1|^2 |a2|^2
    float d10 = 0.f, d11 = 0.f;                  // a0.a1, a1.a2
    float d20 = 0.f, d21 = 0.f;                  // a0.c0, a1.c1
    float m0 = 0.f, m1 = 0.f;                    // |c0|^2, |c1|^2

#pragma unroll
    for (int k = 0; k < 2 * NPL; k++) {
        const float2 a0 = A0[32 * k];
        const float2 a1 = A1[32 * k];
        const float2 a2 = A2[32 * k];
        const float2 c0 = C0[32 * k];
        const float2 c1 = C1[32 * k];
        n0  = fmaf(a0.x, a0.x, n0);  n0  = fmaf(a0.y, a0.y, n0);
        n1  = fmaf(a1.x, a1.x, n1);  n1  = fmaf(a1.y, a1.y, n1);
        n2  = fmaf(a2.x, a2.x, n2);  n2  = fmaf(a2.y, a2.y, n2);
        d10 = fmaf(a0.x, a1.x, d10); d10 = fmaf(a0.y, a1.y, d10);
        d11 = fmaf(a1.x, a2.x, d11); d11 = fmaf(a1.y, a2.y, d11);
        d20 = fmaf(a0.x, c0.x, d20); d20 = fmaf(a0.y, c0.y, d20);
        d21 = fmaf(a1.x, c1.x, d21); d21 = fmaf(a1.y, c1.y, d21);
        m0  = fmaf(c0.x, c0.x, m0);  m0  = fmaf(c0.y, c0.y, m0);
        m1  = fmaf(c1.x, c1.x, m1);  m1  = fmaf(c1.y, c1.y, m1);
    }

#pragma unroll
    for (int off = 16; off > 0; off >>= 1) {
        n0  += __shfl_xor_sync(0xFFFFFFFFu, n0,  off);
        n1  += __shfl_xor_sync(0xFFFFFFFFu, n1,  off);
        n2  += __shfl_xor_sync(0xFFFFFFFFu, n2,  off);
        d10 += __shfl_xor_sync(0xFFFFFFFFu, d10, off);
        d11 += __shfl_xor_sync(0xFFFFFFFFu, d11, off);
        d20 += __shfl_xor_sync(0xFFFFFFFFu, d20, off);
        d21 += __shfl_xor_sync(0xFFFFFFFFu, d21, off);
        m0  += __shfl_xor_sync(0xFFFFFFFFu, m0,  off);
        m1  += __shfl_xor_sync(0xFFFFFFFFu, m1,  off);
    }

    if (lane == 0) {
        if (v0) {
            const float nA0 = fmaxf(sqrtf(n0), EPSN);
            outR[t0] = vr0 ? d10 / (nA0 * fmaxf(sqrtf(n1), EPSN)) : -1.0f;
            outD[t0] = vd0 ? d20 / (nA0 * fmaxf(sqrtf(m0), EPSN)) : -1.0f;
        }
        if (v1) {
            const float nA1 = fmaxf(sqrtf(n1), EPSN);
            outR[t1] = vr1 ? d11 / (nA1 * fmaxf(sqrtf(n2), EPSN)) : -1.0f;
            outD[t1] = vd1 ? d21 / (nA1 * fmaxf(sqrtf(m1), EPSN)) : -1.0f;
        }
    }
}

template <int NPL>  // D = NPL * 128 floats
__global__ void __launch_bounds__(256, 5) simdiff_pair2_kernel(
    const float* __restrict__ x,
    const int* __restrict__ p_frames,
    const int* __restrict__ p_height,
    const int* __restrict__ p_width,
    const int* __restrict__ p_interval,
    float* __restrict__ out,
    int total)
{
    const int width  = *p_width;
    const int height = *p_height;
    const int frames = *p_frames;
    const int iv     = *p_interval;
    const int tpf    = width * height;

    const int wib  = threadIdx.x >> 5;      // 0..7
    const int lane = threadIdx.x & 31;

    float* __restrict__ outR = out;
    float* __restrict__ outD = out + total;

    if (iv == 1 && width >= 2) {
        // ---- paired-diagonal 2-step tiling ----
        const int W1 = width - 1;
        const int ndelta = frames + tpf - 1;           // delta' = i-f+frames-1
        const int nq  = (ndelta + 2 * W1 - 1) / (2 * W1);
        const int nFb = (frames + 7) >> 3;             // frame blocks of 8
        const long ntile = (long)nq * W1 * nFb;

        const int dtok = tpf + 1;
        const int ctok = tpf + width;

        const int half = wib >> 2;          // 0 = chain A, 1 = chain B
        const int kk   = wib & 3;           // step-pair slot

        for (long p = blockIdx.x; p < ntile; p += gridDim.x) {
            const long t1q = p / W1;
            const int  r   = (int)(p - t1q * W1);
            const int  sb  = (int)(t1q / nq);
            const int  q   = (int)(t1q - (long)sb * nq);

            const int dp = q * 2 * W1 + r + half * W1;  // this half's delta'
            const int f0 = 8 * sb + 2 * kk;
            const int f1 = f0 + 1;
            const int i0 = f0 + dp - (frames - 1);
            const int i1 = i0 + 1;

            const bool v0 = (f0 < frames) && (i0 >= 0) && (i0 < tpf);
            const bool v1 = (f1 < frames) && (i1 >= 0) && (i1 < tpf);
            if (!v0 && !v1) continue;

            const int t0 = f0 * tpf + i0;   // OOB if !v0 (never dereferenced)
            const int t1 = f1 * tpf + i1;   // OOB if !v1

            const bool vf0 = v0 && (f1 < frames);
            const bool vr0 = vf0 && (i1 < tpf);       // right-target == t1
            const bool vd0 = vf0 && (i0 < tpf - width);
            const bool vf1 = v1 && (f1 + 1 < frames);
            const bool vr1 = vf1 && (i1 + 1 < tpf);
            const bool vd1 = vf1 && (i1 < tpf - width);

            const int tsafe = v0 ? t0 : t1;
            const int ta0 = v0  ? t0 : tsafe;
            const int ta1 = v1  ? t1 : tsafe;          // vr0 implies v1
            const int ta2 = vr1 ? t1 + dtok : tsafe;
            const int tc0 = vd0 ? t0 + ctok : tsafe;
            const int tc1 = vd1 ? t1 + ctok : tsafe;

            body2<NPL>(x, outR, outD, t0, t1, ta0, ta1, ta2, tc0, tc1,
                       v0, v1, vr0, vd0, vr1, vd1, lane);
        }
    } else {
        // ---- general-iv fallback: R14 lattice 2-step decode (proven) ----
        const int nch_a = iv * tpf;
        const int nch_b = frames > iv ? frames - iv : 0;
        const int nch   = nch_a + nch_b;
        const int maxL  = min((frames + iv - 1) / iv, tpf);
        const int ncb = (nch + 1) >> 1;
        const int nsb = (maxL + 7) >> 3;
        const long ntile = (long)ncb * nsb;

        const int jj = wib & 1;
        const int kk = wib >> 1;
        const int dtok = iv * tpf + 1;
        const int ctok = iv * tpf + width;

        for (long p = blockIdx.x; p < ntile; p += gridDim.x) {
            const int cb = (int)(p % ncb);
            const int sb = (int)(p / ncb);

            const int ci = cb * 2 + jj;
            if (ci >= nch) continue;

            int f0c, i0c;
            if (ci < nch_a) { f0c = ci % iv; i0c = ci / iv; }
            else            { f0c = iv + (ci - nch_a); i0c = 0; }
            if (f0c >= frames || i0c >= tpf) continue;

            const int Lc = min((frames - f0c + iv - 1) / iv, tpf - i0c);
            const int s0 = sb * 8 + kk * 2;
            if (s0 >= Lc) continue;

            const int fA = f0c + s0 * iv;
            const int iA = i0c + s0;
            const int t0 = fA * tpf + iA;

            const bool vf0 = (fA + iv) < frames;
            const bool vr0 = vf0 && (iA + 1 < tpf);
            const bool vd0 = vf0 && (iA < tpf - width);

            const int t1  = t0 + dtok;
            const bool v1 = vr0;                       // token1 exists iff vr0
            const bool vf1 = v1 && ((fA + 2 * iv) < frames);
            const bool vr1 = vf1 && (iA + 2 < tpf);
            const bool vd1 = vf1 && (iA + 1 < tpf - width);

            const int ta1 = v1  ? t1 : t0;
            const int ta2 = vr1 ? t1 + dtok : ta1;
            const int tc0 = vd0 ? t0 + ctok : t0;
            const int tc1 = vd1 ? t1 + ctok : t0;

            body2<NPL>(x, outR, outD, t0, t1, t0, ta1, ta2, tc0, tc1,
                       true, v1, vr0, vd0, vr1, vd1, lane);
        }
    }
}

// Generic fallback for arbitrary D (scalar loads, one warp per token).
__global__ void __launch_bounds__(256) simdiff_generic_kernel(
    const float* __restrict__ x,
    const int* __restrict__ p_frames,
    const int* __restrict__ p_height,
    const int* __restrict__ p_width,
    const int* __restrict__ p_interval,
    float* __restrict__ out,
    int total, int D)
{
    const int gwarp = (blockIdx.x * blockDim.x + threadIdx.x) >> 5;
    const int lane  = threadIdx.x & 31;
    if (gwarp >= total) return;

    const int width    = *p_width;
    const int height   = *p_height;
    const int frames   = *p_frames;
    const int interval = *p_interval;
    const int tpf      = width * height;

    const int f = gwarp / tpf;
    const int i = gwarp - f * tpf;

    float* __restrict__ outR = out;
    float* __restrict__ outD = out + total;

    const bool vf = (f + interval) < frames;
    if (!vf) {
        if (lane == 0) { outR[gwarp] = -1.0f; outD[gwarp] = -1.0f; }
        return;
    }
    const bool vr = (i < tpf - 1);
    const bool vd = (i < tpf - width);

    const size_t bframe = (size_t)(f + interval) * tpf + i;
    const size_t i1 = vr ? (bframe + 1)     : bframe;
    const size_t i2 = vd ? (bframe + width) : bframe;

    const float* a = x + (size_t)gwarp * D;
    const float* b = x + i1 * D;
    const float* c = x + i2 * D;

    float na = 0.0f, d1 = 0.0f, n1 = 0.0f, d2 = 0.0f, n2 = 0.0f;
    for (int k = lane; k < D; k += 32) {
        float av = a[k], bv = b[k], cv = c[k];
        na = fmaf(av, av, na);
        d1 = fmaf(av, bv, d1); n1 = fmaf(bv, bv, n1);
        d2 = fmaf(av, cv, d2); n2 = fmaf(cv, cv, n2);
    }

#pragma unroll
    for (int off = 16; off > 0; off >>= 1) {
        na += __shfl_xor_sync(0xFFFFFFFFu, na, off);
        d1 += __shfl_xor_sync(0xFFFFFFFFu, d1, off);
        n1 += __shfl_xor_sync(0xFFFFFFFFu, n1, off);
        d2 += __shfl_xor_sync(0xFFFFFFFFu, d2, off);
        n2 += __shfl_xor_sync(0xFFFFFFFFu, n2, off);
    }

    if (lane == 0) {
        const float nA = fmaxf(sqrtf(na), EPSN);
        outR[gwarp] = vr ? d1 / (nA * fmaxf(sqrtf(n1), EPSN)) : -1.0f;
        outD[gwarp] = vd ? d2 / (nA * fmaxf(sqrtf(n2), EPSN)) : -1.0f;
    }
}

extern "C" void kernel_launch(void* const* d_in, const int* in_sizes, int n_in,
                              void* d_out, int out_size) {
    const float* x        = (const float*)d_in[0];
    const int* p_frames   = (const int*)d_in[1];
    const int* p_height   = (const int*)d_in[2];
    const int* p_width    = (const int*)d_in[3];
    const int* p_interval = (const int*)d_in[4];
    float* out = (float*)d_out;

    const int total = out_size / 2;            // frames * tpf
    const int D     = in_sizes[0] / total;     // hidden dim

    if (D == 1152 || D == 1024 || D == 1280) {
        // ~total/16 useful tiles + diagonal-edge padding; grid-stride
        // covers any shape, surplus tiles exit immediately.
        const int blocks = total / 16 + 1024;
        if (D == 1152) {
            simdiff_pair2_kernel<9><<<blocks, 256>>>(
                x, p_frames, p_height, p_width, p_interval, out, total);
        } else if (D == 1024) {
            simdiff_pair2_kernel<8><<<blocks, 256>>>(
                x, p_frames, p_height, p_width, p_interval, out, total);
        } else {
            simdiff_pair2_kernel<10><<<blocks, 256>>>(
                x, p_frames, p_height, p_width, p_interval, out, total);
        }
    } else {
        const int blocks = (total + 7) / 8;
        simdiff_generic_kernel<<<blocks, 256>>>(
            x, p_frames, p_height, p_width, p_interval, out, total, D);
    }
}